// round 8
// baseline (speedup 1.0000x reference)
#include <cuda_runtime.h>
#include <cuda_fp16.h>
#include <cuda.h>
#include <cstdint>
#include <dlfcn.h>

// ---------------------------------------------------------------------------
// out[8192,1024] = SiLU(x)@Wb^T + einsum('bik,oik->bo', basis(x), Ws)
// One GEMM: C = A @ W^T, A[8192,9216] fp16, W[1024,9216] fp16 (basis-major K).
// sm_103 (no tcgen05): TMA + mbarrier warp-specialized pipeline feeding
// mma.sync HMMA. R8: 16 consumer warps (4/SMSP), closed-form B-spline prep.
// ---------------------------------------------------------------------------
#define B_ROWS 8192
#define IN_F   1024
#define OUT_F  1024
#define KDIM   9216

__device__ __align__(1024) __half g_A[(size_t)B_ROWS * KDIM];   // 144 MB
__device__ __align__(1024) __half g_W[(size_t)OUT_F * KDIM];    // 18 MB

// ===========================================================================
// PTX helpers
// ===========================================================================
__device__ __forceinline__ uint32_t smem_u32(const void* p) {
    uint32_t a;
    asm("{ .reg .u64 t; cvta.to.shared.u64 t, %1; cvt.u32.u64 %0, t; }" : "=r"(a) : "l"(p));
    return a;
}
__device__ __forceinline__ uint32_t elect_one() {
    uint32_t pred;
    asm volatile("{\n .reg .pred p;\n elect.sync _|p, 0xFFFFFFFF;\n selp.b32 %0, 1, 0, p;\n}" : "=r"(pred));
    return pred;
}
#define MBAR_INIT(addr, cnt) \
    asm volatile("mbarrier.init.shared.b64 [%0], %1;" :: "r"(addr), "r"((uint32_t)(cnt)) : "memory")
#define MBAR_EXPECT_TX(addr, bytes) \
    asm volatile("mbarrier.arrive.expect_tx.shared.b64 _, [%0], %1;" :: "r"(addr), "r"((uint32_t)(bytes)) : "memory")
#define MBAR_ARRIVE(addr) \
    asm volatile("mbarrier.arrive.shared.b64 _, [%0];" :: "r"(addr) : "memory")
#define MBAR_WAIT(addr, parity) do {                                          \
    uint32_t _m = (addr); uint32_t _p = (parity); uint32_t _d;                \
    asm volatile("{\n .reg .pred p;\n"                                        \
        " mbarrier.try_wait.parity.acquire.cta.shared::cta.b64 p, [%1], %2;\n"\
        " selp.b32 %0, 1, 0, p;\n}" : "=r"(_d) : "r"(_m), "r"(_p) : "memory");\
    if (!_d) {                                                                \
        asm volatile("{\n .reg .pred P1;\n"                                   \
        "WL_%=:\n"                                                            \
        " mbarrier.try_wait.parity.acquire.cta.shared::cta.b64 P1, [%0], %1, 0x989680;\n" \
        " @P1 bra.uni WD_%=;\n bra.uni WL_%=;\nWD_%=:\n}"                     \
        :: "r"(_m), "r"(_p) : "memory");                                      \
    } } while (0)

__device__ __forceinline__ void tma_load_2d(uint32_t dst, const void* map,
                                            int cx, int cy, uint32_t mbar) {
    asm volatile(
        "cp.async.bulk.tensor.2d.shared::cta.global.tile.mbarrier::complete_tx::bytes "
        "[%0], [%1, {%2, %3}], [%4];"
        :: "r"(dst), "l"(map), "r"(cx), "r"(cy), "r"(mbar) : "memory");
}

__device__ __forceinline__ void mma16816(float* c, const uint32_t* a, const uint32_t* b) {
    asm volatile(
        "mma.sync.aligned.m16n8k16.row.col.f32.f16.f16.f32 "
        "{%0,%1,%2,%3}, {%4,%5,%6,%7}, {%8,%9}, {%0,%1,%2,%3};\n"
        : "+f"(c[0]), "+f"(c[1]), "+f"(c[2]), "+f"(c[3])
        : "r"(a[0]), "r"(a[1]), "r"(a[2]), "r"(a[3]), "r"(b[0]), "r"(b[1]));
}
__device__ __forceinline__ void ldsm_x4(uint32_t* r, uint32_t addr) {
    asm volatile("ldmatrix.sync.aligned.m8n8.x4.shared.b16 {%0,%1,%2,%3}, [%4];"
        : "=r"(r[0]), "=r"(r[1]), "=r"(r[2]), "=r"(r[3]) : "r"(addr));
}

// ===========================================================================
// Closed-form cubic B-spline: for xc in interval iv (of 5), the only nonzero
// basis values are out[iv..iv+3] = N0..N3(u), the cardinal cubics.
// Algebraically identical to the Cox-de-Boor recursion on this uniform grid.
// ===========================================================================
__device__ __forceinline__ void bspline8_fast(float v, float* b) {
#pragma unroll
    for (int j = 0; j < 8; j++) b[j] = 0.0f;
    float xc = fminf(fmaxf(v, -1.0f), 1.0f);
    float t = (xc + 1.0f) * 2.5f;          // in [0,5]
    int iv = (int)t; if (iv > 4) iv = 4;
    float u = t - (float)iv;               // in [0,1]
    float um = 1.0f - u;
    float u2 = u * u, u3 = u2 * u;
    float N0 = um * um * um * 0.16666667f;
    float N1 = 0.5f * u3 - u2 + 0.66666667f;
    float N2 = -0.5f * u3 + 0.5f * u2 + 0.5f * u + 0.16666667f;
    float N3 = u3 * 0.16666667f;
    switch (iv) {
        case 0: b[0]=N0; b[1]=N1; b[2]=N2; b[3]=N3; break;
        case 1: b[1]=N0; b[2]=N1; b[3]=N2; b[4]=N3; break;
        case 2: b[2]=N0; b[3]=N1; b[4]=N2; b[5]=N3; break;
        case 3: b[3]=N0; b[4]=N1; b[5]=N2; b[6]=N3; break;
        default:b[4]=N0; b[5]=N1; b[6]=N2; b[7]=N3; break;
    }
}

// ===========================================================================
// Prep kernels: 8 input elements per thread, uint4 (16B) stores per stream.
// ===========================================================================
__global__ void prep_A_kernel(const float* __restrict__ x) {
    int idx = blockIdx.x * blockDim.x + threadIdx.x;   // 8192*128
    if (idx >= B_ROWS * (IN_F / 8)) return;
    int b = idx >> 7;
    int blk = idx & 127;
    const float4* xp = reinterpret_cast<const float4*>(x + (size_t)b * IN_F + blk * 8);
    float4 v0 = xp[0], v1 = xp[1];
    float xs[8] = {v0.x, v0.y, v0.z, v0.w, v1.x, v1.y, v1.z, v1.w};

    float sil[8];
    float bas[8][8];
#pragma unroll
    for (int e = 0; e < 8; e++) {
        float v = xs[e];
        sil[e] = v / (1.0f + __expf(-v));
        bspline8_fast(v, bas[e]);
    }

    uint4* row = reinterpret_cast<uint4*>(g_A + (size_t)b * KDIM);
    {
        __align__(16) __half2 h[4];
#pragma unroll
        for (int q = 0; q < 4; q++) h[q] = __floats2half2_rn(sil[2 * q], sil[2 * q + 1]);
        row[blk] = *reinterpret_cast<uint4*>(h);
    }
#pragma unroll
    for (int j = 0; j < 8; j++) {
        __align__(16) __half2 h[4];
#pragma unroll
        for (int q = 0; q < 4; q++) h[q] = __floats2half2_rn(bas[2 * q][j], bas[2 * q + 1][j]);
        row[(j + 1) * 128 + blk] = *reinterpret_cast<uint4*>(h);
    }
}

__global__ void prep_W_kernel(const float* __restrict__ base_w,
                              const float* __restrict__ spline_w) {
    int idx = blockIdx.x * blockDim.x + threadIdx.x;   // 1024*128
    if (idx >= OUT_F * (IN_F / 8)) return;
    int o = idx >> 7;
    int blk = idx & 127;
    const float4* bp = reinterpret_cast<const float4*>(base_w + (size_t)o * IN_F + blk * 8);
    float4 w0 = bp[0], w1 = bp[1];
    float bw[8] = {w0.x, w0.y, w0.z, w0.w, w1.x, w1.y, w1.z, w1.w};

    float s[64];
    const float4* sp = reinterpret_cast<const float4*>(
        spline_w + ((size_t)o * IN_F + blk * 8) * 8);
#pragma unroll
    for (int q = 0; q < 16; q++) {
        float4 v = sp[q];
        s[q * 4 + 0] = v.x; s[q * 4 + 1] = v.y; s[q * 4 + 2] = v.z; s[q * 4 + 3] = v.w;
    }

    uint4* row = reinterpret_cast<uint4*>(g_W + (size_t)o * KDIM);
    {
        __align__(16) __half2 h[4];
#pragma unroll
        for (int q = 0; q < 4; q++) h[q] = __floats2half2_rn(bw[2 * q], bw[2 * q + 1]);
        row[blk] = *reinterpret_cast<uint4*>(h);
    }
#pragma unroll
    for (int j = 0; j < 8; j++) {
        __align__(16) __half2 h[4];
#pragma unroll
        for (int q = 0; q < 4; q++)
            h[q] = __floats2half2_rn(s[(2 * q) * 8 + j], s[(2 * q + 1) * 8 + j]);
        row[(j + 1) * 128 + blk] = *reinterpret_cast<uint4*>(h);
    }
}

// ===========================================================================
// GEMM: TMA producer warp + 16 mma.sync consumer warps (4/SMSP), 6-stage ring.
// Tile: BM=128, BN=128, BK=64 halves (128B rows, SW128). Warp tile 32x32.
// Swizzle: 16B chunk' = chunk ^ (row & 7).
// ===========================================================================
#define BM 128
#define BN 128
#define BK 64
#define NSTG 6
#define KTILES (KDIM / BK)                    // 144
#define A_BYTES (BM * BK * 2)                 // 16384
#define B_BYTES (BN * BK * 2)                 // 16384
#define STG_BYTES (A_BYTES + B_BYTES)         // 32768
#define SMEM_BARS 1024
#define SMEM_TOTAL (SMEM_BARS + NSTG * STG_BYTES)   // 197632

__global__ void __launch_bounds__(544, 1) gemm_kernel(
    const __grid_constant__ CUtensorMap tmA,
    const __grid_constant__ CUtensorMap tmB,
    float* __restrict__ C)
{
    extern __shared__ __align__(1024) char smem[];
    const uint32_t sb = smem_u32(smem);
    const uint32_t FULL  = sb;          // 6 x 8B
    const uint32_t EMPTY = sb + 64;     // 6 x 8B
    const uint32_t STG0  = sb + SMEM_BARS;

    const int tid = threadIdx.x;
    const int wid = tid >> 5;
    const int lane = tid & 31;
    const int bm = blockIdx.y;
    const int bn = blockIdx.x;

    if (tid == 0) {
#pragma unroll
        for (int s = 0; s < NSTG; s++) {
            MBAR_INIT(FULL + 8 * s, 1);
            MBAR_INIT(EMPTY + 8 * s, 16);
        }
    }
    __syncthreads();

    if (wid == 16) {
        // ---------------- producer ----------------
        if (elect_one()) {
            int st = 0, ph = 1;                 // phase 1: first empty-wait passes
            for (int s = 0; s < KTILES; s++) {
                MBAR_WAIT(EMPTY + 8 * st, ph);
                const uint32_t buf = STG0 + st * STG_BYTES;
                MBAR_EXPECT_TX(FULL + 8 * st, STG_BYTES);
                tma_load_2d(buf, &tmA, s * BK, bm * BM, FULL + 8 * st);
                tma_load_2d(buf + A_BYTES, &tmB, s * BK, bn * BN, FULL + 8 * st);
                if (++st == NSTG) { st = 0; ph ^= 1; }
            }
        }
        return;
    }

    // ---------------- consumers (warps 0..15), warp tile 32x32 ----------------
    const int grp = lane >> 2;
    const int thr = lane & 3;
    const int wm = (wid & 3) * 32;
    const int wn = (wid >> 2) * 32;

    const int hiA = lane >> 4;              // A chunk half (0/1)
    const int hiB = (lane >> 3) & 1;        // B chunk half (0/1)
    uint32_t aoff[2]; int ax7[2];
#pragma unroll
    for (int im = 0; im < 2; im++) {
        int r = wm + (lane & 15) + im * 16;
        aoff[im] = (uint32_t)r * 128;
        ax7[im] = r & 7;
    }
    uint32_t boff[2]; int bx7[2];
#pragma unroll
    for (int p = 0; p < 2; p++) {
        int r = wn + p * 16 + ((lane >> 4) << 3) + (lane & 7);
        boff[p] = (uint32_t)r * 128;
        bx7[p] = r & 7;
    }

    float acc[2][4][4];
#pragma unroll
    for (int im = 0; im < 2; im++)
#pragma unroll
        for (int in = 0; in < 4; in++)
#pragma unroll
            for (int r = 0; r < 4; r++) acc[im][in][r] = 0.0f;

    int st = 0, ph = 0;
#pragma unroll 1
    for (int s = 0; s < KTILES; s++) {
        MBAR_WAIT(FULL + 8 * st, ph);
        const uint32_t bufA = STG0 + st * STG_BYTES;
        const uint32_t bufB = bufA + A_BYTES;
#pragma unroll
        for (int ks = 0; ks < 4; ks++) {
            const int cb = 2 * ks;            // base 16B chunk of this k16 step
            uint32_t af[2][4];
#pragma unroll
            for (int im = 0; im < 2; im++)
                ldsm_x4(af[im], bufA + aoff[im] +
                        (uint32_t)(((cb + hiA) ^ ax7[im]) << 4));
            uint32_t bq[2][4];
#pragma unroll
            for (int p = 0; p < 2; p++)
                ldsm_x4(bq[p], bufB + boff[p] +
                        (uint32_t)(((cb + hiB) ^ bx7[p]) << 4));
#pragma unroll
            for (int im = 0; im < 2; im++)
#pragma unroll
                for (int p = 0; p < 2; p++) {
                    uint32_t b0[2] = {bq[p][0], bq[p][1]};
                    uint32_t b1[2] = {bq[p][2], bq[p][3]};
                    mma16816(acc[im][2 * p + 0], af[im], b0);
                    mma16816(acc[im][2 * p + 1], af[im], b1);
                }
        }
        if (lane == 0) MBAR_ARRIVE(EMPTY + 8 * st);
        if (++st == NSTG) { st = 0; ph ^= 1; }
    }

    // epilogue
#pragma unroll
    for (int im = 0; im < 2; im++) {
        int row0 = bm * BM + wm + im * 16 + grp;
#pragma unroll
        for (int in = 0; in < 4; in++) {
            int col = bn * BN + wn + in * 8 + thr * 2;
            float2 v0 = make_float2(acc[im][in][0], acc[im][in][1]);
            float2 v1 = make_float2(acc[im][in][2], acc[im][in][3]);
            *(float2*)&C[(size_t)row0 * OUT_F + col] = v0;
            *(float2*)&C[(size_t)(row0 + 8) * OUT_F + col] = v1;
        }
    }
}

// ===========================================================================
// Host side
// ===========================================================================
typedef CUresult (*EncodeTiledFn)(
    CUtensorMap*, CUtensorMapDataType, cuuint32_t, void*,
    const cuuint64_t*, const cuuint64_t*, const cuuint32_t*, const cuuint32_t*,
    CUtensorMapInterleave, CUtensorMapSwizzle, CUtensorMapL2promotion,
    CUtensorMapFloatOOBfill);

static EncodeTiledFn get_encode_fn() {
    static EncodeTiledFn fn = nullptr;
    if (!fn) {
        void* h = dlopen("libcuda.so.1", RTLD_NOW | RTLD_GLOBAL);
        if (!h) h = dlopen("libcuda.so", RTLD_NOW | RTLD_GLOBAL);
        if (h) fn = (EncodeTiledFn)dlsym(h, "cuTensorMapEncodeTiled");
    }
    return fn;
}

static void make_map(CUtensorMap* map, void* base, uint64_t rows, uint32_t box_rows) {
    cuuint64_t dims[2]    = {(cuuint64_t)KDIM, (cuuint64_t)rows};
    cuuint64_t strides[1] = {(cuuint64_t)KDIM * sizeof(__half)};
    cuuint32_t box[2]     = {(cuuint32_t)BK, box_rows};
    cuuint32_t estr[2]    = {1, 1};
    get_encode_fn()(map, CU_TENSOR_MAP_DATA_TYPE_FLOAT16, 2, base,
                    dims, strides, box, estr,
                    CU_TENSOR_MAP_INTERLEAVE_NONE, CU_TENSOR_MAP_SWIZZLE_128B,
                    CU_TENSOR_MAP_L2_PROMOTION_L2_128B,
                    CU_TENSOR_MAP_FLOAT_OOB_FILL_NONE);
}

extern "C" void kernel_launch(void* const* d_in, const int* in_sizes, int n_in,
                              void* d_out, int out_size) {
    const float* x        = (const float*)d_in[0];   // (8192, 1024)
    const float* base_w   = (const float*)d_in[1];   // (1024, 1024)
    const float* spline_w = (const float*)d_in[2];   // (1024, 1024, 8)
    float* out            = (float*)d_out;           // (8192, 1024)

    void *pA = nullptr, *pW = nullptr;
    cudaGetSymbolAddress(&pA, g_A);
    cudaGetSymbolAddress(&pW, g_W);

    CUtensorMap tmA, tmB;
    make_map(&tmA, pA, B_ROWS, BM);
    make_map(&tmB, pW, OUT_F, BN);

    cudaFuncSetAttribute(gemm_kernel,
                         cudaFuncAttributeMaxDynamicSharedMemorySize, SMEM_TOTAL);

    prep_W_kernel<<<(OUT_F * (IN_F / 8) + 255) / 256, 256>>>(base_w, spline_w);
    prep_A_kernel<<<(B_ROWS * (IN_F / 8) + 255) / 256, 256>>>(x);

    dim3 grid(OUT_F / BN, B_ROWS / BM);   // (8, 64)
    gemm_kernel<<<grid, 544, SMEM_TOTAL>>>(tmA, tmB, out);
}